// round 1
// baseline (speedup 1.0000x reference)
#include <cuda_runtime.h>
#include <math.h>

// ---------------------------------------------------------------------------
// m_btabl: BL layer (relu(W1 @ x @ W2 + B)) + TABL head, fused.
// Strategy:
//   * prep kernel: max_norm scaling of the 5 weight matrices, build Wm,
//     clamp lambda, store packed layouts in __device__ globals.
//   * main kernel: 160 threads = 32 samples x 5 t-columns. Each thread owns
//     one t-column of one sample: y1 column (40 floats) in registers, all
//     reductions done with packed fma.rn.f32x2 over the d-dimension.
//     Weights broadcast from smem (LDS.128, warp-uniform addresses).
//   * tiny per-sample tail (attention softmax + output softmax) on 32 threads
//     via an smem exchange buffer.
// ---------------------------------------------------------------------------

#define D1v 40
#define T1v 10
#define D2v 120
#define T2v 5
#define D3v 3

#define BLK 160      // threads per block (32 samples * 5 t)
#define SPT 32       // samples per tile
#define TPB 4        // tiles per block -> 128 samples per block
#define XSTR 404     // padded x row stride in floats (404 mod 32 = 20: conflict-free)

// smem layout (float offsets)
#define SW1   0                      // 4800  scaled BL_W1 [120][40]
#define SBo   4800                   // 600   BL_B [120][5] (raw)
#define STW   5400                   // 480   scaled T_W1 transposed+padded [120][4]
#define SW2o  5880                   // 50    scaled BL_W2 [10][5]
#define SWM   5936                   // 25    Wm [5][5]
#define SW2B  5968                   // 5     scaled T_W2
#define STBo  5976                   // 3     T_B
#define SLAM  5980                   // 1     lambda
#define SXo   5984                   // 32*404 = 12928  staged x tile
#define XCHo  (SXo + SPT*XSTR)       // 18912: 32*16 exchange for X3
#define SMEM_FLOATS (XCHo + SPT*16)  // 19424 floats = 77696 bytes

typedef unsigned long long ull;

__device__ __forceinline__ ull pk2(float lo, float hi){
    ull r; asm("mov.b64 %0, {%1,%2};" : "=l"(r) : "f"(lo), "f"(hi)); return r;
}
__device__ __forceinline__ float2 upk2(ull v){
    float2 r; asm("mov.b64 {%0,%1}, %2;" : "=f"(r.x), "=f"(r.y) : "l"(v)); return r;
}
__device__ __forceinline__ ull ffma2(ull a, ull b, ull c){
    ull d; asm("fma.rn.f32x2 %0, %1, %2, %3;" : "=l"(d) : "l"(a), "l"(b), "l"(c)); return d;
}
__device__ __forceinline__ ull fmul2(ull a, ull b){
    ull d; asm("mul.rn.f32x2 %0, %1, %2;" : "=l"(d) : "l"(a), "l"(b)); return d;
}
__device__ __forceinline__ ull fadd2(ull a, ull b){
    ull d; asm("add.rn.f32x2 %0, %1, %2;" : "=l"(d) : "l"(a), "l"(b)); return d;
}

// ----------------- preprocessed weights (device globals) -------------------
__device__ float gW1[D2v*D1v];    // scaled BL_W1, row-major [e][d]
__device__ float gW2[T1v*T2v];    // scaled BL_W2 [k][t]
__device__ float gTW1p[D2v*4];    // scaled T_W1 as [e][j], j padded to 4 (pad=0)
__device__ float gWm[T2v*T2v];
__device__ float gW2b[T2v];
__device__ float gTB[D3v];
__device__ float gLam;

__global__ void prep_kernel(const float* __restrict__ W1, const float* __restrict__ W2,
                            const float* __restrict__ TW1, const float* __restrict__ TW,
                            const float* __restrict__ TW2, const float* __restrict__ TB,
                            const float* __restrict__ l)
{
    __shared__ float red[512];
    const int tid = threadIdx.x;

    auto nscale = [&](const float* p, int n) -> float {
        float s = 0.f;
        for (int i = tid; i < n; i += 512) s += p[i] * p[i];
        red[tid] = s; __syncthreads();
        for (int o = 256; o > 0; o >>= 1) {
            if (tid < o) red[tid] += red[tid + o];
            __syncthreads();
        }
        float nn = sqrtf(red[0]);
        float sc = (nn > 10.f) ? (10.f / (1e-8f + nn)) : 1.f;
        __syncthreads();
        return sc;
    };

    float s1 = nscale(W1,  D2v*D1v);
    float s2 = nscale(W2,  T1v*T2v);
    float s3 = nscale(TW1, D3v*D2v);
    float s4 = nscale(TW,  T2v*T2v);
    float s5 = nscale(TW2, T2v);

    for (int i = tid; i < D2v*D1v; i += 512) gW1[i] = W1[i] * s1;
    for (int i = tid; i < T1v*T2v; i += 512) gW2[i] = W2[i] * s2;
    for (int i = tid; i < D2v*4;   i += 512) {
        int e = i >> 2, j = i & 3;
        gTW1p[i] = (j < 3) ? TW1[j*D2v + e] * s3 : 0.f;
    }
    for (int i = tid; i < T2v*T2v; i += 512) {
        int r = i / T2v, c = i % T2v;
        gWm[i] = (r == c) ? (1.f / T2v) : TW[i] * s4;   // diag forced to 1/t1
    }
    if (tid < T2v) gW2b[tid] = TW2[tid] * s5;
    if (tid < D3v) gTB[tid]  = TB[tid];
    if (tid == 0) {
        float lv = l[0];
        gLam = fminf(fmaxf(lv, 0.f), 1.f);
    }
}

// --------------------------------- main ------------------------------------
__global__ void __launch_bounds__(BLK, 2)
main_kernel(const float* __restrict__ x, const float* __restrict__ Bb,
            float* __restrict__ out)
{
    extern __shared__ float sm[];
    const int tid = threadIdx.x;

    // cooperative weight load -> smem
    for (int i = tid; i < D2v*D1v; i += BLK) sm[SW1 + i] = gW1[i];
    for (int i = tid; i < D2v*T2v; i += BLK) sm[SBo + i] = Bb[i];
    for (int i = tid; i < D2v*4;   i += BLK) sm[STW + i] = gTW1p[i];
    if (tid < 50)                        sm[SW2o + tid]        = gW2[tid];
    else if (tid >= 64  && tid < 89)     sm[SWM  + (tid - 64)] = gWm[tid - 64];
    else if (tid >= 96  && tid < 101)    sm[SW2B + (tid - 96)] = gW2b[tid - 96];
    else if (tid >= 104 && tid < 107)    sm[STBo + (tid - 104)] = gTB[tid - 104];
    else if (tid == 112)                 sm[SLAM] = gLam;
    __syncthreads();

    const int sl = tid / T2v;            // local sample 0..31
    const int tt = tid - sl * T2v;       // t-column 0..4

    // per-thread packed W2 column: w2c[p] = (W2[2p][tt], W2[2p+1][tt])
    ull w2c[5];
    #pragma unroll
    for (int p = 0; p < 5; p++)
        w2c[p] = pk2(sm[SW2o + (2*p)*T2v + tt], sm[SW2o + (2*p+1)*T2v + tt]);

    const long long blk_base = (long long)blockIdx.x * (SPT * TPB);

    for (int tile = 0; tile < TPB; tile++) {
        const long long tbase = blk_base + (long long)tile * SPT;

        // ---- stage x tile: 32 samples * 400 floats, contiguous in global ----
        {
            const float4* xs  = (const float4*)(x + tbase * (D1v * T1v));
            float4*       sx4 = (float4*)(sm + SXo);
            #pragma unroll
            for (int it = 0; it < 20; it++) {
                int i = tid + it * BLK;          // 0..3199
                int s = i / 100;
                int o = i - s * 100;
                sx4[s * 101 + o] = xs[i];        // padded row stride 404 floats
            }
        }
        __syncthreads();   // sync1: x ready (also orders prev-tile xch reads)

        // ---- GEMM1: y1 column (packed pairs over d) ----
        const float* myx = sm + SXo + sl * XSTR;
        ull y2[20];        // y2[q] = (y1[2q], y1[2q+1])
        #pragma unroll
        for (int q = 0; q < 20; q++) {
            const ull* xr0 = (const ull*)(myx + (2*q)   * T1v);
            const ull* xr1 = (const ull*)(myx + (2*q+1) * T1v);
            ull a = fmul2(xr0[0], w2c[0]);
            ull b = fmul2(xr1[0], w2c[0]);
            #pragma unroll
            for (int p = 1; p < 5; p++) {
                a = ffma2(xr0[p], w2c[p], a);
                b = ffma2(xr1[p], w2c[p], b);
            }
            float2 ca = upk2(a), cb = upk2(b);
            y2[q] = pk2(ca.x + ca.y, cb.x + cb.y);
        }

        // ---- GEMM2 (h = relu(W1a@y1 + B)) streamed + X3 = T_W1 @ h ----
        ull Xp0 = 0ULL, Xp1 = 0ULL;              // (X3[0],X3[1]) , (X3[2],pad)
        const float* bp = sm + SBo + tt;
        #pragma unroll 4
        for (int e = 0; e < D2v; e++) {
            const ulonglong2* w = (const ulonglong2*)(sm + SW1 + e * D1v);
            ulonglong2 wp0 = w[0];
            ull a = fmul2(y2[0], wp0.x);
            ull b = fmul2(y2[1], wp0.y);
            #pragma unroll
            for (int i = 1; i < 10; i++) {
                ulonglong2 wp = w[i];
                a = ffma2(y2[2*i],   wp.x, a);
                b = ffma2(y2[2*i+1], wp.y, b);
            }
            float2 c = upk2(fadd2(a, b));
            float h = fmaxf(c.x + c.y + bp[e * T2v], 0.f);
            ull hd = pk2(h, h);
            ulonglong2 tw = ((const ulonglong2*)(sm + STW))[e];
            Xp0 = ffma2(tw.x, hd, Xp0);
            Xp1 = ffma2(tw.y, hd, Xp1);          // pad weight is 0 -> lane stays 0
        }

        // exchange X3 columns
        {
            float2 X01 = upk2(Xp0), X2z = upk2(Xp1);
            float* xc = sm + XCHo + sl * 16;
            xc[0*T2v + tt] = X01.x;
            xc[1*T2v + tt] = X01.y;
            xc[2*T2v + tt] = X2z.x;
        }
        __syncthreads();   // sync2: xch ready

        // ---- per-sample tail: attention + output softmax (32 threads) ----
        if (tid < SPT) {
            const float* xr = sm + XCHo + tid * 16;
            float X[3][5];
            #pragma unroll
            for (int j = 0; j < 3; j++)
                #pragma unroll
                for (int t = 0; t < 5; t++)
                    X[j][t] = xr[j*5 + t];

            const float lam = sm[SLAM];
            float o3[3];
            #pragma unroll
            for (int j = 0; j < 3; j++) {
                float P[5];
                #pragma unroll
                for (int tp = 0; tp < 5; tp++) {
                    float s = 0.f;
                    #pragma unroll
                    for (int t = 0; t < 5; t++) s += X[j][t] * sm[SWM + t*5 + tp];
                    P[tp] = s;
                }
                float m = P[0];
                #pragma unroll
                for (int tp = 1; tp < 5; tp++) m = fmaxf(m, P[tp]);
                float A[5]; float ssum = 0.f;
                #pragma unroll
                for (int tp = 0; tp < 5; tp++) { A[tp] = __expf(P[tp] - m); ssum += A[tp]; }
                float inv = __fdividef(1.f, ssum);
                float acc = sm[STBo + j];
                #pragma unroll
                for (int t = 0; t < 5; t++) {
                    float Xc = X[j][t] * (lam + (1.f - lam) * A[t] * inv);
                    acc += Xc * sm[SW2B + t];
                }
                o3[j] = acc;
            }
            float m  = fmaxf(o3[0], fmaxf(o3[1], o3[2]));
            float e0 = __expf(o3[0] - m);
            float e1 = __expf(o3[1] - m);
            float e2 = __expf(o3[2] - m);
            float inv = __fdividef(1.f, e0 + e1 + e2);
            long long gs = tbase + tid;
            out[gs*3 + 0] = e0 * inv;
            out[gs*3 + 1] = e1 * inv;
            out[gs*3 + 2] = e2 * inv;
        }
        // next iteration's x-load is safe: everyone passed sync2 (GEMM1 done),
        // and xch(t+1) writes happen only after sync1(t+1), after tail reads.
    }
}

// ------------------------------ launch --------------------------------------
extern "C" void kernel_launch(void* const* d_in, const int* in_sizes, int n_in,
                              void* d_out, int out_size)
{
    const float* x   = (const float*)d_in[0];
    const float* W1  = (const float*)d_in[1];
    const float* W2  = (const float*)d_in[2];
    const float* Bb  = (const float*)d_in[3];
    const float* TW1 = (const float*)d_in[4];
    const float* TW  = (const float*)d_in[5];
    const float* TW2 = (const float*)d_in[6];
    const float* TB  = (const float*)d_in[7];
    const float* l   = (const float*)d_in[8];

    const int nsamp = in_sizes[0] / (D1v * T1v);   // 131072

    cudaFuncSetAttribute(main_kernel, cudaFuncAttributeMaxDynamicSharedMemorySize,
                         SMEM_FLOATS * 4);

    prep_kernel<<<1, 512>>>(W1, W2, TW1, TW, TW2, TB, l);

    const int grid = nsamp / (SPT * TPB);          // 1024
    main_kernel<<<grid, BLK, SMEM_FLOATS * 4>>>(x, Bb, (float*)d_out);
}